// round 2
// baseline (speedup 1.0000x reference)
#include <cuda_runtime.h>
#include <cuda_bf16.h>

// Problem constants (fixed by the dataset)
#define HID    32
#define NIRR   16
#define OUTC   32
#define FANIN  (HID * NIRR)      // 512
#define MAX_ATOMS 50000

// Scratch: A[a][i*32+c] = sum_h nf[a][h] * W[(h*16+i)*32+c]
__device__ float g_A[(size_t)MAX_ATOMS * FANIN];

// ---------------------------------------------------------------------------
// Kernel 0: out[t, c] = b[c]
// ---------------------------------------------------------------------------
__global__ void init_out_kernel(float* __restrict__ out,
                                const float* __restrict__ b, int n) {
    int t = blockIdx.x * blockDim.x + threadIdx.x;
    if (t < n) out[t] = __ldg(&b[t & (OUTC - 1)]);
}

// ---------------------------------------------------------------------------
// Kernel 1: A = NF @ W'   (M=50000, K=32, N=512)
// Each thread owns 2 output columns (W columns in registers), 4 atoms per
// inner iteration, nf tile staged in shared memory.
// ---------------------------------------------------------------------------
__global__ void __launch_bounds__(256, 4)
precompute_A_kernel(const float* __restrict__ nf,
                    const float* __restrict__ W, int n_atoms) {
    const int tid = threadIdx.x;
    const int n0 = tid * 2;          // columns n0, n0+1 of A (0..511)
    const int n1 = n0 + 1;

    // W columns for this thread, all h: w[h][0..1]
    float w0[HID], w1[HID];
#pragma unroll
    for (int h = 0; h < HID; h++) {
        w0[h] = __ldg(&W[(h * NIRR + (n0 >> 5)) * OUTC + (n0 & 31)]);
        w1[h] = __ldg(&W[(h * NIRR + (n1 >> 5)) * OUTC + (n1 & 31)]);
    }

    __shared__ float snf[4 * HID];

    for (int a0 = blockIdx.x * 4; a0 < n_atoms; a0 += gridDim.x * 4) {
        __syncthreads();
        if (tid < 4 * HID) {
            int a = a0 + (tid >> 5);
            snf[tid] = (a < n_atoms) ? nf[(size_t)a * HID + (tid & 31)] : 0.0f;
        }
        __syncthreads();

        float acc00 = 0.f, acc01 = 0.f, acc10 = 0.f, acc11 = 0.f;
        float acc20 = 0.f, acc21 = 0.f, acc30 = 0.f, acc31 = 0.f;
#pragma unroll
        for (int h = 0; h < HID; h++) {
            float f0 = snf[0 * HID + h];
            float f1 = snf[1 * HID + h];
            float f2 = snf[2 * HID + h];
            float f3 = snf[3 * HID + h];
            acc00 = fmaf(f0, w0[h], acc00); acc01 = fmaf(f0, w1[h], acc01);
            acc10 = fmaf(f1, w0[h], acc10); acc11 = fmaf(f1, w1[h], acc11);
            acc20 = fmaf(f2, w0[h], acc20); acc21 = fmaf(f2, w1[h], acc21);
            acc30 = fmaf(f3, w0[h], acc30); acc31 = fmaf(f3, w1[h], acc31);
        }
        if (a0 + 0 < n_atoms)
            *(float2*)&g_A[(size_t)(a0 + 0) * FANIN + n0] = make_float2(acc00, acc01);
        if (a0 + 1 < n_atoms)
            *(float2*)&g_A[(size_t)(a0 + 1) * FANIN + n0] = make_float2(acc10, acc11);
        if (a0 + 2 < n_atoms)
            *(float2*)&g_A[(size_t)(a0 + 2) * FANIN + n0] = make_float2(acc20, acc21);
        if (a0 + 3 < n_atoms)
            *(float2*)&g_A[(size_t)(a0 + 3) * FANIN + n0] = make_float2(acc30, acc31);
    }
}

// ---------------------------------------------------------------------------
// Kernel 2: per-edge contribution.
// One warp per edge, lane = output channel c.
// contrib[c] = sum_i Y[i] * A[src, i*32 + c];  atomicAdd into out[tgt, c].
// edge_index is int32 (the harness downcasts int64 -> int32).
// ---------------------------------------------------------------------------
__global__ void __launch_bounds__(256)
edge_kernel(const float* __restrict__ ev,
            const int* __restrict__ eidx,
            float* __restrict__ out,
            int n_edges, int n_atoms) {
    const int warp = (blockIdx.x * blockDim.x + threadIdx.x) >> 5;
    const int lane = threadIdx.x & 31;
    if (warp >= n_edges) return;

    const int src = eidx[warp];
    const int tgt = eidx[n_edges + warp];
    // Safety: never dereference OOB (turns a dtype surprise into a wrong
    // answer instead of an illegal access).
    if ((unsigned)src >= (unsigned)n_atoms || (unsigned)tgt >= (unsigned)n_atoms)
        return;

    const float ex = __ldg(&ev[(size_t)warp * 3 + 0]);
    const float ey = __ldg(&ev[(size_t)warp * 3 + 1]);
    const float ez = __ldg(&ev[(size_t)warp * 3 + 2]);

    float r = sqrtf(ex * ex + ey * ey + ez * ez);
    float inv = 1.0f / fmaxf(r, 1e-12f);
    float x = ex * inv, y = ey * inv, z = ez * inv;
    float x2 = x * x, y2 = y * y, z2 = z * z;

    float Y[NIRR];
    Y[0]  = 0.28209479177387814f;
    Y[1]  = 0.4886025119029199f * y;
    Y[2]  = 0.4886025119029199f * z;
    Y[3]  = 0.4886025119029199f * x;
    Y[4]  = 1.0925484305920792f * x * y;
    Y[5]  = 1.0925484305920792f * y * z;
    Y[6]  = 0.31539156525252005f * (3.0f * z2 - 1.0f);
    Y[7]  = 1.0925484305920792f * x * z;
    Y[8]  = 0.5462742152960396f * (x2 - y2);
    Y[9]  = 0.5900435899266435f * y * (3.0f * x2 - y2);
    Y[10] = 2.890611442640554f  * x * y * z;
    Y[11] = 0.4570457994644658f * y * (5.0f * z2 - 1.0f);
    Y[12] = 0.3731763325901154f * z * (5.0f * z2 - 3.0f);
    Y[13] = 0.4570457994644658f * x * (5.0f * z2 - 1.0f);
    Y[14] = 1.445305721320277f  * z * (x2 - y2);
    Y[15] = 0.5900435899266435f * x * (x2 - 3.0f * y2);

    const float* __restrict__ Arow = g_A + (size_t)src * FANIN + lane;
    float acc = 0.f;
#pragma unroll
    for (int i = 0; i < NIRR; i++)
        acc = fmaf(Y[i], __ldg(&Arow[i * OUTC]), acc);

    atomicAdd(&out[(size_t)tgt * OUTC + lane], acc);
}

// ---------------------------------------------------------------------------
// Launcher
// Inputs (metadata order): node_features f32 [n_atoms,32], edge_vectors f32
// [n_edges,3], edge_index int32 [2,n_edges], W f32 [512,32], b f32 [32].
// Output: f32 [n_atoms, 32].
// ---------------------------------------------------------------------------
extern "C" void kernel_launch(void* const* d_in, const int* in_sizes, int n_in,
                              void* d_out, int out_size) {
    const float* nf  = (const float*)d_in[0];
    const float* ev  = (const float*)d_in[1];
    const int*   ei  = (const int*)d_in[2];
    const float* W   = (const float*)d_in[3];
    const float* b   = (const float*)d_in[4];
    float*       out = (float*)d_out;

    const int n_atoms = in_sizes[0] / HID;
    const int n_edges = in_sizes[1] / 3;

    // out = b (broadcast)
    {
        int n = out_size;
        init_out_kernel<<<(n + 255) / 256, 256>>>(out, b, n);
    }

    // A = NF @ W'
    {
        int grid = (n_atoms + 3) / 4;
        if (grid > 1184) grid = 1184;   // grid-stride, ~8 blocks/SM
        precompute_A_kernel<<<grid, 256>>>(nf, W, n_atoms);
    }

    // per-edge gather + scatter
    {
        int warps_per_block = 256 / 32;
        int grid = (n_edges + warps_per_block - 1) / warps_per_block;
        edge_kernel<<<grid, 256>>>(ev, ei, out, n_edges, n_atoms);
    }
}

// round 3
// speedup vs baseline: 1.2862x; 1.2862x over previous
#include <cuda_runtime.h>
#include <cuda_fp16.h>
#include <cuda_bf16.h>

// Problem constants (fixed by the dataset)
#define HID    32
#define NIRR   16
#define OUTC   32
#define FANIN  (HID * NIRR)      // 512
#define MAX_ATOMS 50000

// Scratch: A[a][i*32+c] = sum_h nf[a][h] * W[(h*16+i)*32+c], stored fp16.
// Row = 512 halves = 1024 B = 8 x 128B lines.
__device__ __half g_Ah[(size_t)MAX_ATOMS * FANIN];

// ---------------------------------------------------------------------------
// Kernel 0: out[t, c] = b[c]
// ---------------------------------------------------------------------------
__global__ void init_out_kernel(float* __restrict__ out,
                                const float* __restrict__ b, int n) {
    int t = blockIdx.x * blockDim.x + threadIdx.x;
    if (t < n) out[t] = __ldg(&b[t & (OUTC - 1)]);
}

// ---------------------------------------------------------------------------
// Kernel 1: A = NF @ W'   (M=50000, K=32, N=512), output fp16.
// Each thread owns 2 adjacent output columns (same irrep, channels c, c+1),
// W columns in registers, 4 atoms per inner iteration, nf tile in smem.
// ---------------------------------------------------------------------------
__global__ void __launch_bounds__(256, 4)
precompute_A_kernel(const float* __restrict__ nf,
                    const float* __restrict__ W, int n_atoms) {
    const int tid = threadIdx.x;
    const int n0 = tid * 2;          // columns n0, n0+1 of A (0..511), n0 even
    const int n1 = n0 + 1;

    float w0[HID], w1[HID];
#pragma unroll
    for (int h = 0; h < HID; h++) {
        w0[h] = __ldg(&W[(h * NIRR + (n0 >> 5)) * OUTC + (n0 & 31)]);
        w1[h] = __ldg(&W[(h * NIRR + (n1 >> 5)) * OUTC + (n1 & 31)]);
    }

    __shared__ float snf[4 * HID];

    for (int a0 = blockIdx.x * 4; a0 < n_atoms; a0 += gridDim.x * 4) {
        __syncthreads();
        if (tid < 4 * HID) {
            int a = a0 + (tid >> 5);
            snf[tid] = (a < n_atoms) ? nf[(size_t)a * HID + (tid & 31)] : 0.0f;
        }
        __syncthreads();

        float acc00 = 0.f, acc01 = 0.f, acc10 = 0.f, acc11 = 0.f;
        float acc20 = 0.f, acc21 = 0.f, acc30 = 0.f, acc31 = 0.f;
#pragma unroll
        for (int h = 0; h < HID; h++) {
            float f0 = snf[0 * HID + h];
            float f1 = snf[1 * HID + h];
            float f2 = snf[2 * HID + h];
            float f3 = snf[3 * HID + h];
            acc00 = fmaf(f0, w0[h], acc00); acc01 = fmaf(f0, w1[h], acc01);
            acc10 = fmaf(f1, w0[h], acc10); acc11 = fmaf(f1, w1[h], acc11);
            acc20 = fmaf(f2, w0[h], acc20); acc21 = fmaf(f2, w1[h], acc21);
            acc30 = fmaf(f3, w0[h], acc30); acc31 = fmaf(f3, w1[h], acc31);
        }
        if (a0 + 0 < n_atoms)
            *(__half2*)&g_Ah[(size_t)(a0 + 0) * FANIN + n0] = __floats2half2_rn(acc00, acc01);
        if (a0 + 1 < n_atoms)
            *(__half2*)&g_Ah[(size_t)(a0 + 1) * FANIN + n0] = __floats2half2_rn(acc10, acc11);
        if (a0 + 2 < n_atoms)
            *(__half2*)&g_Ah[(size_t)(a0 + 2) * FANIN + n0] = __floats2half2_rn(acc20, acc21);
        if (a0 + 3 < n_atoms)
            *(__half2*)&g_Ah[(size_t)(a0 + 3) * FANIN + n0] = __floats2half2_rn(acc30, acc31);
    }
}

// ---------------------------------------------------------------------------
// Kernel 2: per-edge contribution. One warp per edge.
// Lane layout: cpair = lane & 15 (channel pair), half_sel = lane >> 4 (irrep
// parity). 8 x LDG.32 (__half2) per lane; each warp LDG covers exactly one
// contiguous 128B line of the A row. shfl_xor(16) folds the two irrep
// parities; each lane then atomically adds its single channel.
// ---------------------------------------------------------------------------
__global__ void __launch_bounds__(256)
edge_kernel(const float* __restrict__ ev,
            const int* __restrict__ eidx,
            float* __restrict__ out,
            int n_edges, int n_atoms) {
    const int warp = (blockIdx.x * blockDim.x + threadIdx.x) >> 5;
    const int lane = threadIdx.x & 31;
    if (warp >= n_edges) return;

    const int src = eidx[warp];
    const int tgt = eidx[n_edges + warp];
    if ((unsigned)src >= (unsigned)n_atoms || (unsigned)tgt >= (unsigned)n_atoms)
        return;

    const float ex = __ldg(&ev[(size_t)warp * 3 + 0]);
    const float ey = __ldg(&ev[(size_t)warp * 3 + 1]);
    const float ez = __ldg(&ev[(size_t)warp * 3 + 2]);

    float r = sqrtf(ex * ex + ey * ey + ez * ez);
    float inv = 1.0f / fmaxf(r, 1e-12f);
    float x = ex * inv, y = ey * inv, z = ez * inv;
    float x2 = x * x, y2 = y * y, z2 = z * z;

    float Y[NIRR];
    Y[0]  = 0.28209479177387814f;
    Y[1]  = 0.4886025119029199f * y;
    Y[2]  = 0.4886025119029199f * z;
    Y[3]  = 0.4886025119029199f * x;
    Y[4]  = 1.0925484305920792f * x * y;
    Y[5]  = 1.0925484305920792f * y * z;
    Y[6]  = 0.31539156525252005f * (3.0f * z2 - 1.0f);
    Y[7]  = 1.0925484305920792f * x * z;
    Y[8]  = 0.5462742152960396f * (x2 - y2);
    Y[9]  = 0.5900435899266435f * y * (3.0f * x2 - y2);
    Y[10] = 2.890611442640554f  * x * y * z;
    Y[11] = 0.4570457994644658f * y * (5.0f * z2 - 1.0f);
    Y[12] = 0.3731763325901154f * z * (5.0f * z2 - 3.0f);
    Y[13] = 0.4570457994644658f * x * (5.0f * z2 - 1.0f);
    Y[14] = 1.445305721320277f  * z * (x2 - y2);
    Y[15] = 0.5900435899266435f * x * (x2 - 3.0f * y2);

    const int cpair    = lane & 15;   // channel pair: channels 2*cpair, 2*cpair+1
    const int half_sel = lane >> 4;   // irrep parity

    // half2 pointer into this src's A row
    const __half2* __restrict__ Arow =
        (const __half2*)(g_Ah + (size_t)src * FANIN);

    // Batch the 8 loads for MLP, then FMA.
    __half2 v[8];
#pragma unroll
    for (int ip = 0; ip < 8; ip++) {
        int irr = ip * 2 + half_sel;          // this lane's irrep
        v[ip] = __ldg(&Arow[irr * (OUTC / 2) + cpair]);
    }

    float accx = 0.f, accy = 0.f;
#pragma unroll
    for (int ip = 0; ip < 8; ip++) {
        // compile-time pair, runtime select (FSEL, no local-mem spill)
        float yi = half_sel ? Y[ip * 2 + 1] : Y[ip * 2];
        float2 f = __half22float2(v[ip]);
        accx = fmaf(yi, f.x, accx);
        accy = fmaf(yi, f.y, accy);
    }

    // Fold the two irrep parities: lanes l and l^16 hold the same channels.
    accx += __shfl_xor_sync(0xFFFFFFFFu, accx, 16);
    accy += __shfl_xor_sync(0xFFFFFFFFu, accy, 16);

    // Lane writes channel c = 2*cpair + half_sel
    float val = half_sel ? accy : accx;
    atomicAdd(&out[(size_t)tgt * OUTC + cpair * 2 + half_sel], val);
}

// ---------------------------------------------------------------------------
// Launcher
// Inputs (metadata order): node_features f32 [n_atoms,32], edge_vectors f32
// [n_edges,3], edge_index int32 [2,n_edges], W f32 [512,32], b f32 [32].
// Output: f32 [n_atoms, 32].
// ---------------------------------------------------------------------------
extern "C" void kernel_launch(void* const* d_in, const int* in_sizes, int n_in,
                              void* d_out, int out_size) {
    const float* nf  = (const float*)d_in[0];
    const float* ev  = (const float*)d_in[1];
    const int*   ei  = (const int*)d_in[2];
    const float* W   = (const float*)d_in[3];
    const float* b   = (const float*)d_in[4];
    float*       out = (float*)d_out;

    const int n_atoms = in_sizes[0] / HID;
    const int n_edges = in_sizes[1] / 3;

    // out = b (broadcast)
    {
        int n = out_size;
        init_out_kernel<<<(n + 255) / 256, 256>>>(out, b, n);
    }

    // A = NF @ W' (fp16 output)
    {
        int grid = (n_atoms + 3) / 4;
        if (grid > 1184) grid = 1184;   // grid-stride, ~8 blocks/SM
        precompute_A_kernel<<<grid, 256>>>(nf, W, n_atoms);
    }

    // per-edge gather + scatter
    {
        int warps_per_block = 256 / 32;
        int grid = (n_edges + warps_per_block - 1) / warps_per_block;
        edge_kernel<<<grid, 256>>>(ev, ei, out, n_edges, n_atoms);
    }
}

// round 4
// speedup vs baseline: 2.0311x; 1.5792x over previous
#include <cuda_runtime.h>
#include <cuda_fp16.h>
#include <cuda_bf16.h>

// Problem constants (fixed by the dataset)
#define HID    32
#define NIRR   16
#define OUTC   32
#define FANIN  (HID * NIRR)      // 512
#define MAX_ATOMS 50000

// Scratch: A[a][i*32+c] = sum_h nf[a][h] * W[(h*16+i)*32+c], stored fp16.
// Row = 512 halves = 1024 B = 8 x 128B lines. Line l holds irreps 2l, 2l+1.
__device__ __half g_Ah[(size_t)MAX_ATOMS * FANIN];

// ---------------------------------------------------------------------------
// Kernel 0: out[t, c] = b[c]   (float4 vectorized; OUTC=32 -> 8 float4 / row)
// ---------------------------------------------------------------------------
__global__ void init_out_kernel(float4* __restrict__ out4,
                                const float4* __restrict__ b4, int n4) {
    int t = blockIdx.x * blockDim.x + threadIdx.x;
    if (t < n4) out4[t] = __ldg(&b4[t & 7]);
}

// ---------------------------------------------------------------------------
// Kernel 1: A = NF @ W'   (M=50000, K=32, N=512), output fp16.
// ---------------------------------------------------------------------------
__global__ void __launch_bounds__(256, 4)
precompute_A_kernel(const float* __restrict__ nf,
                    const float* __restrict__ W, int n_atoms) {
    const int tid = threadIdx.x;
    const int n0 = tid * 2;          // columns n0, n0+1 of A (0..511), n0 even
    const int n1 = n0 + 1;

    float w0[HID], w1[HID];
#pragma unroll
    for (int h = 0; h < HID; h++) {
        w0[h] = __ldg(&W[(h * NIRR + (n0 >> 5)) * OUTC + (n0 & 31)]);
        w1[h] = __ldg(&W[(h * NIRR + (n1 >> 5)) * OUTC + (n1 & 31)]);
    }

    __shared__ float snf[4 * HID];

    for (int a0 = blockIdx.x * 4; a0 < n_atoms; a0 += gridDim.x * 4) {
        __syncthreads();
        if (tid < 4 * HID) {
            int a = a0 + (tid >> 5);
            snf[tid] = (a < n_atoms) ? nf[(size_t)a * HID + (tid & 31)] : 0.0f;
        }
        __syncthreads();

        float acc00 = 0.f, acc01 = 0.f, acc10 = 0.f, acc11 = 0.f;
        float acc20 = 0.f, acc21 = 0.f, acc30 = 0.f, acc31 = 0.f;
#pragma unroll
        for (int h = 0; h < HID; h++) {
            float f0 = snf[0 * HID + h];
            float f1 = snf[1 * HID + h];
            float f2 = snf[2 * HID + h];
            float f3 = snf[3 * HID + h];
            acc00 = fmaf(f0, w0[h], acc00); acc01 = fmaf(f0, w1[h], acc01);
            acc10 = fmaf(f1, w0[h], acc10); acc11 = fmaf(f1, w1[h], acc11);
            acc20 = fmaf(f2, w0[h], acc20); acc21 = fmaf(f2, w1[h], acc21);
            acc30 = fmaf(f3, w0[h], acc30); acc31 = fmaf(f3, w1[h], acc31);
        }
        if (a0 + 0 < n_atoms)
            *(__half2*)&g_Ah[(size_t)(a0 + 0) * FANIN + n0] = __floats2half2_rn(acc00, acc01);
        if (a0 + 1 < n_atoms)
            *(__half2*)&g_Ah[(size_t)(a0 + 1) * FANIN + n0] = __floats2half2_rn(acc10, acc11);
        if (a0 + 2 < n_atoms)
            *(__half2*)&g_Ah[(size_t)(a0 + 2) * FANIN + n0] = __floats2half2_rn(acc20, acc21);
        if (a0 + 3 < n_atoms)
            *(__half2*)&g_Ah[(size_t)(a0 + 3) * FANIN + n0] = __floats2half2_rn(acc30, acc31);
    }
}

// ---------------------------------------------------------------------------
// Kernel 2: per-edge contribution. 4 edges per warp, 8 lanes per edge.
//   sub = lane>>3  : edge slot within warp
//   el  = lane&7   : lane within edge group
// A-row gather: 8 x LDG.128 per lane; lane el's uint4 at line l covers
//   irrep = 2l + (el>>2), channels cb..cb+7 where cb = (el&3)*8.
// Fold irrep parity with shfl_xor(4); each lane then owns 4 channels
//   (ch = (el&3)*8 + (el>>2)*4) and issues ONE red.global.add.v4.f32.
// ---------------------------------------------------------------------------
__global__ void __launch_bounds__(256)
edge_kernel(const float* __restrict__ ev,
            const int* __restrict__ eidx,
            float* __restrict__ out,
            int n_edges, int n_atoms) {
    const int lane  = threadIdx.x & 31;
    const int gwarp = (blockIdx.x * blockDim.x + threadIdx.x) >> 5;
    const int sub   = lane >> 3;
    const int el    = lane & 7;
    const int e     = gwarp * 4 + sub;
    if (e >= n_edges) return;                    // whole 8-lane group exits together

    const unsigned gmask = 0xFFu << (sub * 8);   // this edge group's lanes

    const int src = eidx[e];
    const int tgt = eidx[n_edges + e];
    if ((unsigned)src >= (unsigned)n_atoms || (unsigned)tgt >= (unsigned)n_atoms)
        return;

    const float ex = __ldg(&ev[(size_t)e * 3 + 0]);
    const float ey = __ldg(&ev[(size_t)e * 3 + 1]);
    const float ez = __ldg(&ev[(size_t)e * 3 + 2]);

    float r = sqrtf(ex * ex + ey * ey + ez * ez);
    float inv = 1.0f / fmaxf(r, 1e-12f);
    float x = ex * inv, y = ey * inv, z = ez * inv;
    float x2 = x * x, y2 = y * y, z2 = z * z;

    float Y[NIRR];
    Y[0]  = 0.28209479177387814f;
    Y[1]  = 0.4886025119029199f * y;
    Y[2]  = 0.4886025119029199f * z;
    Y[3]  = 0.4886025119029199f * x;
    Y[4]  = 1.0925484305920792f * x * y;
    Y[5]  = 1.0925484305920792f * y * z;
    Y[6]  = 0.31539156525252005f * (3.0f * z2 - 1.0f);
    Y[7]  = 1.0925484305920792f * x * z;
    Y[8]  = 0.5462742152960396f * (x2 - y2);
    Y[9]  = 0.5900435899266435f * y * (3.0f * x2 - y2);
    Y[10] = 2.890611442640554f  * x * y * z;
    Y[11] = 0.4570457994644658f * y * (5.0f * z2 - 1.0f);
    Y[12] = 0.3731763325901154f * z * (5.0f * z2 - 3.0f);
    Y[13] = 0.4570457994644658f * x * (5.0f * z2 - 1.0f);
    Y[14] = 1.445305721320277f  * z * (x2 - y2);
    Y[15] = 0.5900435899266435f * x * (x2 - 3.0f * y2);

    // Gather the A row: 8 uint4 per lane, batched for MLP.
    const uint4* __restrict__ Arow4 =
        (const uint4*)(g_Ah + (size_t)src * FANIN);
    uint4 v[8];
#pragma unroll
    for (int l = 0; l < 8; l++)
        v[l] = __ldg(&Arow4[l * 8 + el]);

    const int par = el >> 2;                     // irrep parity of this lane

    float acc[8];
#pragma unroll
    for (int i = 0; i < 8; i++) acc[i] = 0.f;

#pragma unroll
    for (int l = 0; l < 8; l++) {
        float yi = par ? Y[2 * l + 1] : Y[2 * l];
        float2 f0 = __half22float2(*(const __half2*)&v[l].x);
        float2 f1 = __half22float2(*(const __half2*)&v[l].y);
        float2 f2 = __half22float2(*(const __half2*)&v[l].z);
        float2 f3 = __half22float2(*(const __half2*)&v[l].w);
        acc[0] = fmaf(yi, f0.x, acc[0]); acc[1] = fmaf(yi, f0.y, acc[1]);
        acc[2] = fmaf(yi, f1.x, acc[2]); acc[3] = fmaf(yi, f1.y, acc[3]);
        acc[4] = fmaf(yi, f2.x, acc[4]); acc[5] = fmaf(yi, f2.y, acc[5]);
        acc[6] = fmaf(yi, f3.x, acc[6]); acc[7] = fmaf(yi, f3.y, acc[7]);
    }

    // Fold irrep parity: lanes el and el^4 hold the same 8 channels.
#pragma unroll
    for (int i = 0; i < 8; i++)
        acc[i] += __shfl_xor_sync(gmask, acc[i], 4);

    // Each lane reduces 4 channels: ch_start = (el&3)*8 + par*4.
    float r0 = par ? acc[4] : acc[0];
    float r1 = par ? acc[5] : acc[1];
    float r2 = par ? acc[6] : acc[2];
    float r3 = par ? acc[7] : acc[3];

    float* dst = &out[(size_t)tgt * OUTC + (el & 3) * 8 + par * 4];
    asm volatile("red.global.add.v4.f32 [%0], {%1, %2, %3, %4};"
                 :: "l"(dst), "f"(r0), "f"(r1), "f"(r2), "f"(r3)
                 : "memory");
}

// ---------------------------------------------------------------------------
// Launcher
// Inputs (metadata order): node_features f32 [n_atoms,32], edge_vectors f32
// [n_edges,3], edge_index int32 [2,n_edges], W f32 [512,32], b f32 [32].
// Output: f32 [n_atoms, 32].
// ---------------------------------------------------------------------------
extern "C" void kernel_launch(void* const* d_in, const int* in_sizes, int n_in,
                              void* d_out, int out_size) {
    const float* nf  = (const float*)d_in[0];
    const float* ev  = (const float*)d_in[1];
    const int*   ei  = (const int*)d_in[2];
    const float* W   = (const float*)d_in[3];
    const float* b   = (const float*)d_in[4];
    float*       out = (float*)d_out;

    const int n_atoms = in_sizes[0] / HID;
    const int n_edges = in_sizes[1] / 3;

    // out = b (broadcast), float4
    {
        int n4 = out_size / 4;
        init_out_kernel<<<(n4 + 255) / 256, 256>>>((float4*)out, (const float4*)b, n4);
    }

    // A = NF @ W' (fp16 output)
    {
        int grid = (n_atoms + 3) / 4;
        if (grid > 1184) grid = 1184;   // grid-stride, ~8 blocks/SM
        precompute_A_kernel<<<grid, 256>>>(nf, W, n_atoms);
    }

    // per-edge gather + scatter: 4 edges/warp, 8 warps/block -> 32 edges/block
    {
        int grid = (n_edges + 31) / 32;
        edge_kernel<<<grid, 256>>>(ev, ei, out, n_edges, n_atoms);
    }
}